// round 11
// baseline (speedup 1.0000x reference)
#include <cuda_runtime.h>

typedef unsigned long long ull;

// Chain state: 4-channel fields only. h1 ping-pong, h2 stored per block.
__device__ float g_h1[2][16][4][64][64];   //  2.1 MB
__device__ float g_h2[32][16][4][64][64];  // 33.6 MB

// ---- packed fp32x2 helpers --------------------------------------------------
__device__ __forceinline__ ull ffma2(ull a, ull b, ull c) {
    ull d; asm("fma.rn.f32x2 %0, %1, %2, %3;" : "=l"(d) : "l"(a), "l"(b), "l"(c)); return d;
}
__device__ __forceinline__ ull fadd2(ull a, ull b) {
    ull d; asm("add.rn.f32x2 %0, %1, %2;" : "=l"(d) : "l"(a), "l"(b)); return d;
}
__device__ __forceinline__ ull pack2(float lo, float hi) {
    ull d; asm("mov.b64 %0, {%1, %2};" : "=l"(d) : "f"(lo), "f"(hi)); return d;
}
__device__ __forceinline__ ull dup2(float v) { return pack2(v, v); }
__device__ __forceinline__ ull relu2(ull z) {
    float lo, hi; asm("mov.b64 {%0, %1}, %2;" : "=f"(lo), "=f"(hi) : "l"(z));
    return pack2(fmaxf(lo, 0.f), fmaxf(hi, 0.f));
}
__device__ __forceinline__ ull packmid(ull a, ull b) {
    float alo, ahi, blo, bhi;
    asm("mov.b64 {%0, %1}, %2;" : "=f"(alo), "=f"(ahi) : "l"(a));
    asm("mov.b64 {%0, %1}, %2;" : "=f"(blo), "=f"(bhi) : "l"(b));
    return pack2(ahi, blo);
}

// ---------------------------------------------------------------------------
// k0: h1_0 = relu(W1_0 @ x + b1_0).  Memory-bound (reads x, 67MB).
// ---------------------------------------------------------------------------
__global__ __launch_bounds__(256) void k0_kernel(const float* __restrict__ x,
                                                 const float* __restrict__ w1,
                                                 const float* __restrict__ b1) {
    __shared__ float4 sW1T[256];
    __shared__ float  sB1[4];
    int tid = threadIdx.x;
    if (tid < 4) sB1[tid] = b1[tid];
    sW1T[tid] = make_float4(w1[tid], w1[256 + tid], w1[512 + tid], w1[768 + tid]);
    __syncthreads();

    int n  = blockIdx.x >> 4;
    int yg = blockIdx.x & 15;
    int px = tid & 63;
    int y  = yg * 4 + (tid >> 6);

    const float* xp = x + (size_t)n * 256 * 4096 + y * 64 + px;
    float a0 = sB1[0], a1 = sB1[1], a2 = sB1[2], a3 = sB1[3];
#pragma unroll 8
    for (int c = 0; c < 256; c++) {
        float  xv = xp[c * 4096];
        float4 w  = sW1T[c];
        a0 = fmaf(xv, w.x, a0);
        a1 = fmaf(xv, w.y, a1);
        a2 = fmaf(xv, w.z, a2);
        a3 = fmaf(xv, w.w, a3);
    }
    float* hp = &g_h1[0][n][0][y][px];
    hp[0]     = fmaxf(a0, 0.f);
    hp[4096]  = fmaxf(a1, 0.f);
    hp[8192]  = fmaxf(a2, 0.f);
    hp[12288] = fmaxf(a3, 0.f);
}

// ---------------------------------------------------------------------------
// chain_kernel (block i): HIGH-OCCUPANCY variant.
//   grid 256 = 16 img x 16 tiles (16x16); block 512 = 128 pairs x 4 quarters
//   __launch_bounds__(512,2) -> 2 CTA/SM = 32 warps/SM (occ ~50%)
//   1 pixel-pair + 64 fused channels per thread (latency hidden by warps).
//   Conv: quarter q handles input channel q. Combine/stores balanced: thread
//   (pair,q) owns output channel q. Conv-partial smem reused for fused partials.
// ---------------------------------------------------------------------------
__global__ __launch_bounds__(512, 2) void chain_kernel(
    const float* __restrict__ w1, const float* __restrict__ b1,
    const float* __restrict__ w2, const float* __restrict__ b2,
    const float* __restrict__ w3, const float* __restrict__ b3,
    int blk)
{
    __shared__ __align__(16) float s_h1[4][18][18];  // 5.2 KB
    __shared__ ull        s_w2d[144];                // 1.2 KB  dup-packed conv w
    __shared__ float      s_b2[4];
    __shared__ ulonglong2 s_wall[256][4];            // 16 KB {w3.xy,w3.zw,w1.01,w1.23}
    __shared__ ull        s_b3d[256];                // 2 KB
    __shared__ float      s_b1n[4];
    __shared__ ull        s_cp[4][4][128];           // 16 KB conv partials, REUSED for fused partials

    int tid  = threadIdx.x;
    int pair = tid & 127;         // 0..127
    int q    = tid >> 7;          // 0..3
    int n    = blockIdx.x >> 4;
    int tile = blockIdx.x & 15;
    int ty0  = (tile >> 2) * 16;
    int tx0  = (tile & 3)  * 16;

    // ---- weight staging ----
    if (tid < 144) s_w2d[tid] = dup2(w2[blk * 144 + tid]);
    else if (tid < 148) s_b2[tid - 144] = b2[blk * 4 + (tid - 144)];
    if (blk < 31) {
        if (tid < 256) {
            int c = tid;
            const float* w1n = w1 + (blk + 1) * 1024;
            float4 wr = *(const float4*)&w3[(blk * 256 + c) * 4];
            s_wall[c][0] = make_ulonglong2(dup2(wr.x), dup2(wr.y));
            s_wall[c][1] = make_ulonglong2(dup2(wr.z), dup2(wr.w));
            s_wall[c][2] = make_ulonglong2(dup2(w1n[c]),       dup2(w1n[256 + c]));
            s_wall[c][3] = make_ulonglong2(dup2(w1n[512 + c]), dup2(w1n[768 + c]));
            s_b3d[c]     = dup2(b3[blk * 256 + c]);
        } else if (tid >= 256 && tid < 260) {
            s_b1n[tid - 256] = b1[(blk + 1) * 4 + (tid - 256)];
        }
    }

    // ---- halo tile load: 18x18x4 (zero pad = SAME padding) ----
    const float* h1base = &g_h1[blk & 1][n][0][0][0];
    if (tid < 324) {
        int yy = tid / 18, xx = tid % 18;
        int gy = ty0 + yy - 1, gx = tx0 + xx - 1;
        bool ok = (gy >= 0 && gy < 64 && gx >= 0 && gx < 64);
#pragma unroll
        for (int k = 0; k < 4; k++)
            s_h1[k][yy][xx] = ok ? h1base[k * 4096 + gy * 64 + gx] : 0.f;
    }
    __syncthreads();

    // ---- conv3x3 partial: input channel k = q, this thread's single pair ----
    int py = pair >> 3;
    int x0 = (pair & 7) * 2;
    {
        ull p0 = (q == 0) ? dup2(s_b2[0]) : 0ull;
        ull p1 = (q == 0) ? dup2(s_b2[1]) : 0ull;
        ull p2 = (q == 0) ? dup2(s_b2[2]) : 0ull;
        ull p3 = (q == 0) ? dup2(s_b2[3]) : 0ull;
#pragma unroll
        for (int dy = 0; dy < 3; dy++) {
            const ull* rowp = (const ull*)&s_h1[q][py + dy][x0];
            ull p01 = rowp[0], p23 = rowp[1];
            ull tap0 = p01, tap1 = packmid(p01, p23), tap2 = p23;
            int wi = q * 9 + dy * 3;
            p0 = ffma2(tap0, s_w2d[wi + 0], p0);
            p1 = ffma2(tap0, s_w2d[36 + wi + 0], p1);
            p2 = ffma2(tap0, s_w2d[72 + wi + 0], p2);
            p3 = ffma2(tap0, s_w2d[108 + wi + 0], p3);
            p0 = ffma2(tap1, s_w2d[wi + 1], p0);
            p1 = ffma2(tap1, s_w2d[36 + wi + 1], p1);
            p2 = ffma2(tap1, s_w2d[72 + wi + 1], p2);
            p3 = ffma2(tap1, s_w2d[108 + wi + 1], p3);
            p0 = ffma2(tap2, s_w2d[wi + 2], p0);
            p1 = ffma2(tap2, s_w2d[36 + wi + 2], p1);
            p2 = ffma2(tap2, s_w2d[72 + wi + 2], p2);
            p3 = ffma2(tap2, s_w2d[108 + wi + 2], p3);
        }
        s_cp[q][0][pair] = p0;
        s_cp[q][1][pair] = p1;
        s_cp[q][2][pair] = p2;
        s_cp[q][3][pair] = p3;
    }
    __syncthreads();

    // ---- reduce conv partials: this thread needs ALL four u's ----
    ull u0 = relu2(fadd2(fadd2(s_cp[0][0][pair], s_cp[1][0][pair]),
                         fadd2(s_cp[2][0][pair], s_cp[3][0][pair])));
    ull u1 = relu2(fadd2(fadd2(s_cp[0][1][pair], s_cp[1][1][pair]),
                         fadd2(s_cp[2][1][pair], s_cp[3][1][pair])));
    ull u2 = relu2(fadd2(fadd2(s_cp[0][2][pair], s_cp[1][2][pair]),
                         fadd2(s_cp[2][2][pair], s_cp[3][2][pair])));
    ull u3 = relu2(fadd2(fadd2(s_cp[0][3][pair], s_cp[1][3][pair]),
                         fadd2(s_cp[2][3][pair], s_cp[3][3][pair])));

    // ---- h2 store: thread (pair,q) stores channel q (balanced) ----
    int gy = ty0 + py, gx = tx0 + x0;
    ull uq = (q == 0) ? u0 : (q == 1) ? u1 : (q == 2) ? u2 : u3;
    *(ull*)&g_h2[blk][n][q][gy][gx] = uq;

    __syncthreads();   // everyone done READING s_cp (buffer about to be reused)

    if (blk < 31) {
        ull a0, a1, a2, a3;
        if (q == 0) {
            a0 = dup2(s_b1n[0]); a1 = dup2(s_b1n[1]);
            a2 = dup2(s_b1n[2]); a3 = dup2(s_b1n[3]);
        } else {
            a0 = a1 = a2 = a3 = 0ull;
        }
        int c0 = q << 6;
#pragma unroll 4
        for (int cc = 0; cc < 64; cc++) {
            int c = c0 + cc;
            const ulonglong2* wp = s_wall[c];
            ulonglong2 wA = wp[0], wB = wp[1];
            ull z = ffma2(u0, wA.x, s_b3d[c]);
            z = ffma2(u1, wA.y, z);
            z = ffma2(u2, wB.x, z);
            z = ffma2(u3, wB.y, z);
            ull v = relu2(z);
            ulonglong2 qA = wp[2], qB = wp[3];
            a0 = ffma2(v, qA.x, a0);
            a1 = ffma2(v, qA.y, a1);
            a2 = ffma2(v, qB.x, a2);
            a3 = ffma2(v, qB.y, a3);
        }
        // fused partials into the reused buffer
        s_cp[q][0][pair] = a0;
        s_cp[q][1][pair] = a1;
        s_cp[q][2][pair] = a2;
        s_cp[q][3][pair] = a3;
        __syncthreads();
        // balanced combine: thread (pair,q) finishes output channel q
        ull aq = fadd2(fadd2(s_cp[0][q][pair], s_cp[1][q][pair]),
                       fadd2(s_cp[2][q][pair], s_cp[3][q][pair]));
        *(ull*)&g_h1[(blk + 1) & 1][n][q][gy][gx] = relu2(aq);
    } else {
        __syncthreads();   // uniform barrier count
    }
}

// ---------------------------------------------------------------------------
// acc_kernel: out = sum_i relu(W3_i @ h2_i + b3_i)  (R8 form — ~55% of peak)
// Grid 1024 (16 img x 64 rows), 256 threads = 16 dual-slots x 16 ch-groups.
// ---------------------------------------------------------------------------
__global__ __launch_bounds__(256) void acc_kernel(const float* __restrict__ w3,
                                                  const float* __restrict__ b3,
                                                  float* __restrict__ out) {
    __shared__ ulonglong2 s_w3d[256][2];
    __shared__ ull        s_b3d[256];
    __shared__ __align__(16) float s_u[4][64];

    int tid   = threadIdx.x;
    int n     = blockIdx.x >> 6;
    int y     = blockIdx.x & 63;
    int dual  = tid & 15;
    int grp   = tid >> 4;
    int pxA   = dual * 2;
    int pxB   = pxA + 32;
    int cbase = grp * 16;

    ull accA[16], accB[16];
#pragma unroll
    for (int cc = 0; cc < 16; cc++) { accA[cc] = 0ull; accB[cc] = 0ull; }

    for (int i = 0; i < 32; i++) {
        __syncthreads();
        float4 wr = *(const float4*)&w3[(i * 256 + tid) * 4];
        s_w3d[tid][0] = make_ulonglong2(dup2(wr.x), dup2(wr.y));
        s_w3d[tid][1] = make_ulonglong2(dup2(wr.z), dup2(wr.w));
        s_b3d[tid]    = dup2(b3[i * 256 + tid]);
        s_u[tid >> 6][tid & 63] = g_h2[i][n][tid >> 6][y][tid & 63];
        __syncthreads();

        ull uA0 = *(const ull*)&s_u[0][pxA];
        ull uA1 = *(const ull*)&s_u[1][pxA];
        ull uA2 = *(const ull*)&s_u[2][pxA];
        ull uA3 = *(const ull*)&s_u[3][pxA];
        ull uB0 = *(const ull*)&s_u[0][pxB];
        ull uB1 = *(const ull*)&s_u[1][pxB];
        ull uB2 = *(const ull*)&s_u[2][pxB];
        ull uB3 = *(const ull*)&s_u[3][pxB];
#pragma unroll
        for (int cc = 0; cc < 16; cc++) {
            int c = cbase + cc;
            ulonglong2 wA = s_w3d[c][0], wB = s_w3d[c][1];
            ull bb = s_b3d[c];
            ull zA = ffma2(uA0, wA.x, bb);
            zA = ffma2(uA1, wA.y, zA);
            zA = ffma2(uA2, wB.x, zA);
            zA = ffma2(uA3, wB.y, zA);
            accA[cc] = fadd2(accA[cc], relu2(zA));
            ull zB = ffma2(uB0, wA.x, bb);
            zB = ffma2(uB1, wA.y, zB);
            zB = ffma2(uB2, wB.x, zB);
            zB = ffma2(uB3, wB.y, zB);
            accB[cc] = fadd2(accB[cc], relu2(zB));
        }
    }

#pragma unroll
    for (int cc = 0; cc < 16; cc++) {
        int c = cbase + cc;
        size_t base = (((size_t)n * 256 + c) * 64 + y) * 64;
        *(ull*)&out[base + pxA] = accA[cc];
        *(ull*)&out[base + pxB] = accB[cc];
    }
}

// ---------------------------------------------------------------------------
extern "C" void kernel_launch(void* const* d_in, const int* in_sizes, int n_in,
                              void* d_out, int out_size) {
    const float* x  = (const float*)d_in[0];
    const float* w1 = (const float*)d_in[1];
    const float* b1 = (const float*)d_in[2];
    const float* w2 = (const float*)d_in[3];
    const float* b2 = (const float*)d_in[4];
    const float* w3 = (const float*)d_in[5];
    const float* b3 = (const float*)d_in[6];
    float* out = (float*)d_out;

    k0_kernel<<<256, 256>>>(x, w1, b1);
    for (int i = 0; i < 32; i++)
        chain_kernel<<<256, 512>>>(w1, b1, w2, b2, w3, b3, i);
    acc_kernel<<<1024, 256>>>(w3, b3, out);
}